// round 7
// baseline (speedup 1.0000x reference)
#include <cuda_runtime.h>

// DIRECT implementation of BeatsRandomTokenizer:
//   F = conv(fbank, Wc) [stride 16, VALID] -> F[g][d], g = b*4096 + h*8 + w
//   LN over d (mean+var, eps 1e-5); P = LN(F) @ proj (l2norm(P) skipped:
//   positive per-token scale, argmax-safe); sim = P @ normalize(codebook)^T;
//   out = argmax_k sim.
//
// THIS ROUND: output written as FLOAT32 (value = (float)index). All previous
// rounds' bit-exact rel_err == 1.0 is explained by an int-written buffer being
// compared as float32 (denormals ~ 0).
//
// INPUT RESOLUTION: rank by size (unit-independent): fbank > codebook >
// conv_w = proj (tied pair in encounter order — correct for both dict and
// alphabetical metadata ordering).

#define LN_EPS 1e-5f

__device__ __align__(16) float g_WcT[256 * 512];    // WcT[j][d]
__device__ __align__(16) float g_Cn[256 * 1024];    // Cn[q][k]
__device__ __align__(16) float g_F[65536 * 512];    // conv output
__device__ __align__(16) float g_mu[65536];
__device__ __align__(16) float g_rs[65536];
__device__ __align__(16) float g_PT[256 * 65536];   // PT[q][g]

// ---------------------------------------------------------------------------
__global__ void kWcT(const float* __restrict__ convw) {
    int j = blockIdx.x, t = threadIdx.x;
    g_WcT[j * 512 + t]       = convw[t * 256 + j];
    g_WcT[j * 512 + 256 + t] = convw[(256 + t) * 256 + j];
}

// ---------------------------------------------------------------------------
__global__ void kCn(const float* __restrict__ cb) {
    __shared__ double red[256];
    __shared__ double rn_b;
    int k = blockIdx.x, q = threadIdx.x;
    const float* cbr = cb + (size_t)k * 256;
    double v = (double)cbr[q];
    red[q] = v * v;
    __syncthreads();
    for (int off = 128; off > 0; off >>= 1) {
        if (q < off) red[q] += red[q + off];
        __syncthreads();
    }
    if (q == 0) rn_b = 1.0 / fmax(sqrt(red[0]), 1e-12);
    __syncthreads();
    g_Cn[q * 1024 + k] = (float)((double)cbr[q] * rn_b);
}

// ---------------------------------------------------------------------------
// kF: conv GEMM. Block = 64 tokens x 512 d, K = 256 patch pixels. grid 1024.
// ---------------------------------------------------------------------------
__global__ __launch_bounds__(256) void kF(const float* __restrict__ fbank) {
    __shared__ __align__(16) float Ts[32 * 68];
    __shared__ __align__(16) float Ws[32 * 128];

    int tid = threadIdx.x;
    int ty = tid >> 4, tx = tid & 15;
    int g0 = blockIdx.x * 64;
    int b = g0 >> 12;
    int h0 = (g0 & 4095) >> 3;

    const float4* f4 = (const float4*)(fbank + (size_t)b * 8192 * 128);

    for (int dd = 0; dd < 4; dd++) {
        float acc[4][8];
#pragma unroll
        for (int i = 0; i < 4; i++)
#pragma unroll
            for (int jj = 0; jj < 8; jj++) acc[i][jj] = 0.f;

        for (int kk = 0; kk < 8; kk++) {
            __syncthreads();
#pragma unroll
            for (int p = 0; p < 2; p++) {
                int idx = p * 256 + tid;
                int row = idx >> 5;
                int v = idx & 31;
                int h = row >> 1;
                int r2 = row & 1;
                int r = kk * 2 + r2;
                float4 val = f4[((size_t)(h0 + h) * 16 + r) * 32 + v];
                int e = v * 4;
                int w = e >> 4;
                int c = e & 15;
                int t = h * 8 + w;
                int jl = r2 * 16 + c;
                Ts[(jl + 0) * 68 + t] = val.x;
                Ts[(jl + 1) * 68 + t] = val.y;
                Ts[(jl + 2) * 68 + t] = val.z;
                Ts[(jl + 3) * 68 + t] = val.w;
            }
#pragma unroll
            for (int p = 0; p < 16; p++) {
                int idx = p * 256 + tid;
                int dl = idx & 127;
                int jl = idx >> 7;
                Ws[jl * 128 + dl] =
                    g_WcT[(size_t)(kk * 32 + jl) * 512 + dd * 128 + dl];
            }
            __syncthreads();

#pragma unroll 8
            for (int jl = 0; jl < 32; jl++) {
                float4 a = *(const float4*)&Ts[jl * 68 + ty * 4];
                const float4* Br = (const float4*)&Ws[jl * 128 + tx * 8];
                float4 b0 = Br[0], b1 = Br[1];
                float av[4] = {a.x, a.y, a.z, a.w};
                float bv[8] = {b0.x, b0.y, b0.z, b0.w, b1.x, b1.y, b1.z, b1.w};
#pragma unroll
                for (int i = 0; i < 4; i++)
#pragma unroll
                    for (int jj = 0; jj < 8; jj++)
                        acc[i][jj] = fmaf(av[i], bv[jj], acc[i][jj]);
            }
        }
        __syncthreads();
#pragma unroll
        for (int i = 0; i < 4; i++)
#pragma unroll
            for (int jj = 0; jj < 8; jj++)
                g_F[(size_t)(g0 + ty * 4 + i) * 512 + dd * 128 + tx * 8 + jj] =
                    acc[i][jj];
    }
}

// ---------------------------------------------------------------------------
__global__ __launch_bounds__(256) void kLN() {
    int wid = threadIdx.x >> 5, lane = threadIdx.x & 31;
    int g = blockIdx.x * 8 + wid;
    const float* Fr = g_F + (size_t)g * 512;
    double s1 = 0.0, s2 = 0.0;
#pragma unroll
    for (int i = 0; i < 16; i++) {
        double v = (double)Fr[lane + i * 32];
        s1 += v;
        s2 += v * v;
    }
#pragma unroll
    for (int off = 16; off > 0; off >>= 1) {
        s1 += __shfl_down_sync(0xffffffffu, s1, off);
        s2 += __shfl_down_sync(0xffffffffu, s2, off);
    }
    if (lane == 0) {
        double mu = s1 * (1.0 / 512.0);
        double var = s2 * (1.0 / 512.0) - mu * mu;
        g_mu[g] = (float)mu;
        g_rs[g] = (float)(1.0 / sqrt(var + (double)LN_EPS));
    }
}

// ---------------------------------------------------------------------------
// kP: P = LN(F) @ proj -> PT[q][g]. Block = 64 tok x 256 q. grid 1024.
// ---------------------------------------------------------------------------
__global__ __launch_bounds__(256) void kP(const float* __restrict__ proj) {
    __shared__ __align__(16) float Fs[32 * 68];
    __shared__ __align__(16) float Ps[32 * 128];
    __shared__ float mu_s[64], rs_s[64];

    int tid = threadIdx.x;
    int ty = tid >> 4, tx = tid & 15;
    int g0 = blockIdx.x * 64;

    if (tid < 64) {
        mu_s[tid] = g_mu[g0 + tid];
        rs_s[tid] = g_rs[g0 + tid];
    }

    for (int cc = 0; cc < 2; cc++) {
        float acc[4][8];
#pragma unroll
        for (int i = 0; i < 4; i++)
#pragma unroll
            for (int jj = 0; jj < 8; jj++) acc[i][jj] = 0.f;

        for (int kk = 0; kk < 16; kk++) {
            __syncthreads();
#pragma unroll
            for (int p = 0; p < 8; p++) {
                int idx = p * 256 + tid;
                int dl = idx & 31;
                int t = idx >> 5;
                float v = g_F[(size_t)(g0 + t) * 512 + kk * 32 + dl];
                Fs[dl * 68 + t] = (v - mu_s[t]) * rs_s[t];
            }
#pragma unroll
            for (int p = 0; p < 16; p++) {
                int idx = p * 256 + tid;
                int qv = idx & 127;
                int dl = idx >> 7;
                Ps[dl * 128 + qv] =
                    proj[(size_t)(kk * 32 + dl) * 256 + cc * 128 + qv];
            }
            __syncthreads();

#pragma unroll 8
            for (int dl = 0; dl < 32; dl++) {
                float4 a = *(const float4*)&Fs[dl * 68 + ty * 4];
                const float4* Br = (const float4*)&Ps[dl * 128 + tx * 8];
                float4 b0 = Br[0], b1 = Br[1];
                float av[4] = {a.x, a.y, a.z, a.w};
                float bv[8] = {b0.x, b0.y, b0.z, b0.w, b1.x, b1.y, b1.z, b1.w};
#pragma unroll
                for (int i = 0; i < 4; i++)
#pragma unroll
                    for (int jj = 0; jj < 8; jj++)
                        acc[i][jj] = fmaf(av[i], bv[jj], acc[i][jj]);
            }
        }
        __syncthreads();
#pragma unroll
        for (int jj = 0; jj < 8; jj++) {
            int q = cc * 128 + tx * 8 + jj;
#pragma unroll
            for (int i = 0; i < 4; i++)
                g_PT[(size_t)q * 65536 + g0 + ty * 4 + i] = acc[i][jj];
        }
    }
}

// ---------------------------------------------------------------------------
// kAM: sim = P @ Cn + fused argmax. Block = 64 tok x 1024 codes. grid 1024.
// OUTPUT: float32 index values.
// ---------------------------------------------------------------------------
__global__ __launch_bounds__(256) void kAM(float* __restrict__ out) {
    __shared__ __align__(16) float As[32 * 68];
    __shared__ __align__(16) float Bs[32 * 128];

    int tid = threadIdx.x;
    int ty = tid >> 4, tx = tid & 15;
    int g0 = blockIdx.x * 64;

    float best[4];
    int besti[4];
#pragma unroll
    for (int i = 0; i < 4; i++) { best[i] = -3.4e38f; besti[i] = 0; }

    for (int cc = 0; cc < 8; cc++) {
        float acc[4][8];
#pragma unroll
        for (int i = 0; i < 4; i++)
#pragma unroll
            for (int jj = 0; jj < 8; jj++) acc[i][jj] = 0.f;

        for (int kk = 0; kk < 8; kk++) {
            __syncthreads();
#pragma unroll
            for (int p = 0; p < 8; p++) {
                int idx = p * 256 + tid;
                int t = idx & 63;
                int ql = idx >> 6;
                As[ql * 68 + t] = g_PT[(size_t)(kk * 32 + ql) * 65536 + g0 + t];
            }
#pragma unroll
            for (int p = 0; p < 16; p++) {
                int idx = p * 256 + tid;
                int kv = idx & 127;
                int ql = idx >> 7;
                Bs[ql * 128 + kv] =
                    g_Cn[(size_t)(kk * 32 + ql) * 1024 + cc * 128 + kv];
            }
            __syncthreads();

#pragma unroll 8
            for (int ql = 0; ql < 32; ql++) {
                float4 a = *(const float4*)&As[ql * 68 + ty * 4];
                const float4* Br = (const float4*)&Bs[ql * 128 + tx * 8];
                float4 b0 = Br[0], b1 = Br[1];
                float av[4] = {a.x, a.y, a.z, a.w};
                float bv[8] = {b0.x, b0.y, b0.z, b0.w, b1.x, b1.y, b1.z, b1.w};
#pragma unroll
                for (int i = 0; i < 4; i++)
#pragma unroll
                    for (int jj = 0; jj < 8; jj++)
                        acc[i][jj] = fmaf(av[i], bv[jj], acc[i][jj]);
            }
        }

#pragma unroll
        for (int jj = 0; jj < 8; jj++) {
            int code = cc * 128 + tx * 8 + jj;
#pragma unroll
            for (int i = 0; i < 4; i++)
                if (acc[i][jj] > best[i]) { best[i] = acc[i][jj]; besti[i] = code; }
        }
    }

#pragma unroll
    for (int i = 0; i < 4; i++) {
        float v = best[i];
        int id = besti[i];
#pragma unroll
        for (int off = 8; off > 0; off >>= 1) {
            float v2 = __shfl_down_sync(0xffffffffu, v, off, 16);
            int i2 = __shfl_down_sync(0xffffffffu, id, off, 16);
            if (v2 > v || (v2 == v && i2 < id)) { v = v2; id = i2; }
        }
        if (tx == 0) out[g0 + ty * 4 + i] = (float)id;   // FLOAT32 output
    }
}

// ---------------------------------------------------------------------------
extern "C" void kernel_launch(void* const* d_in, const int* in_sizes, int n_in,
                              void* d_out, int out_size) {
    // Rank-by-size: largest -> fbank; 2nd -> codebook; tied pair -> conv_w,
    // proj in encounter order (valid for dict AND alphabetical ordering).
    int order[8];
    int m = (n_in < 8) ? n_in : 8;
    for (int i = 0; i < m; i++) order[i] = i;
    for (int i = 1; i < m; i++) {
        int key = order[i];
        int j = i - 1;
        while (j >= 0 && in_sizes[order[j]] < in_sizes[key]) {
            order[j + 1] = order[j];
            j--;
        }
        order[j + 1] = key;
    }
    const float* fbank = (const float*)d_in[order[0]];
    const float* cb    = (const float*)d_in[order[1]];
    const float* convw = (const float*)d_in[order[2]];
    const float* proj  = (const float*)d_in[order[3]];
    float* out = (float*)d_out;

    kWcT<<<256, 256>>>(convw);
    kCn<<<1024, 256>>>(cb);
    kF<<<1024, 256>>>(fbank);
    kLN<<<8192, 256>>>();
    kP<<<1024, 256>>>(proj);
    kAM<<<1024, 256>>>(out);
}